// round 12
// baseline (speedup 1.0000x reference)
#include <cuda_runtime.h>
#include <string.h>

#define Bdim 512
#define Ldim 512
#define Tdim 128
#define START_TAG 126
#define STOP_TAG 127
#define LOG2E 1.4426950408889634f
#define LN2   0.6931471805599453f
#define PF 8              // emission prefetch depth / unroll factor
#define NWORK 304         // persistent CTAs (2 per SM)

__device__ float g_partial[Bdim];     // per-batch forward - gold
__device__ int   g_counter;           // work queue head
__device__ int   g_done;              // completion counter
__device__ int   g_order[Bdim];       // batch ids sorted by len desc

__device__ __forceinline__ void fma2(unsigned long long& d,
                                     unsigned long long a,
                                     unsigned long long b) {
    asm("fma.rn.f32x2 %0, %1, %2, %0;" : "+l"(d) : "l"(a), "l"(b));
}
__device__ __forceinline__ float rcp_fast(float x) {
    float r;
    asm("rcp.approx.f32 %0, %1;" : "=f"(r) : "f"(x));
    return r;
}
__device__ __forceinline__ unsigned long long pack2(float a, float b) {
    unsigned long long r;
    asm("mov.b64 %0, {%1,%2};" : "=l"(r) : "f"(a), "f"(b));
    return r;
}
__device__ __forceinline__ float hadd2(unsigned long long a) {
    float2 f; memcpy(&f, &a, 8);
    return f.x + f.y;
}

// Warp-split-K matvec via broadcast LDS from gslice = gbuf + 32*w.
// et[64]: rows 4*lane..4*lane+3 (16 f32x2 pairs each) over this warp's 32 cols.
__device__ __forceinline__ float4 matvec_warp(const float* gslice,
                                              const unsigned long long* et) {
    const ulonglong2* gb = reinterpret_cast<const ulonglong2*>(gslice);
    unsigned long long a0 = 0, a1 = 0, a2 = 0, a3 = 0;
    #pragma unroll
    for (int q = 0; q < 8; q++) {
        ulonglong2 uv = gb[q];            // broadcast LDS.128
        fma2(a0, et[2 * q],          uv.x);
        fma2(a0, et[2 * q + 1],      uv.y);
        fma2(a1, et[16 + 2 * q],     uv.x);
        fma2(a1, et[16 + 2 * q + 1], uv.y);
        fma2(a2, et[32 + 2 * q],     uv.x);
        fma2(a2, et[32 + 2 * q + 1], uv.y);
        fma2(a3, et[48 + 2 * q],     uv.x);
        fma2(a3, et[48 + 2 * q + 1], uv.y);
    }
    return make_float4(hadd2(a0), hadd2(a1), hadd2(a2), hadd2(a3));
}

// terminal LSE + gold score; returns forward_score - gold_score (all threads)
__device__ __forceinline__ float finish_batch(
    float fv, int len, int b, int t, int lane, int warp,
    const float* __restrict__ feats, const float* __restrict__ trans,
    const int* __restrict__ tags, float* smax, float* ssum)
{
    float term = fv + trans[START_TAG * Tdim + t];
    float m2 = term;
    #pragma unroll
    for (int o = 16; o > 0; o >>= 1)
        m2 = fmaxf(m2, __shfl_xor_sync(0xffffffffu, m2, o));
    if (lane == 0) smax[warp] = m2;
    __syncthreads();
    m2 = fmaxf(fmaxf(smax[0], smax[1]), fmaxf(smax[2], smax[3]));

    float ex = exp2f((term - m2) * LOG2E);
    #pragma unroll
    for (int o = 16; o > 0; o >>= 1)
        ex += __shfl_xor_sync(0xffffffffu, ex, o);
    if (lane == 0) ssum[warp] = ex;
    __syncthreads();
    float fwd = m2 + __logf((ssum[0] + ssum[1]) + (ssum[2] + ssum[3]));
    __syncthreads();

    float acc = 0.f;
    const int* tg = tags + b * Ldim;
    for (int j = t; j <= len; j += Tdim) {
        int pa, pb;
        if (j == 0)        { pa = START_TAG;   pb = tg[0];    }
        else if (j == len) { pa = tg[len - 1]; pb = STOP_TAG; }
        else               { pa = tg[j - 1];   pb = tg[j];    }
        acc += trans[pb * Tdim + pa];
    }
    for (int i = t; i < len; i += Tdim) {
        int tag = tg[i];
        acc += feats[((size_t)b * Ldim + i) * Tdim + tag];
    }
    #pragma unroll
    for (int o = 16; o > 0; o >>= 1)
        acc += __shfl_xor_sync(0xffffffffu, acc, o);
    if (lane == 0) ssum[warp] = acc;
    __syncthreads();
    float gold = (ssum[0] + ssum[1]) + (ssum[2] + ssum[3]);
    __syncthreads();
    return fwd - gold;
}

// rank batches by length (desc, stable) + reset counters. grid 8 x 64
__global__ __launch_bounds__(64) void crf_schedule_kernel(const int* __restrict__ lens)
{
    __shared__ int sl[Bdim];
    const int tb = threadIdx.x;
    for (int k = tb; k < Bdim; k += 64) sl[k] = lens[k];
    __syncthreads();
    const int me = blockIdx.x * 64 + tb;
    const int myl = sl[me];
    int rank = 0;
    #pragma unroll 8
    for (int j = 0; j < Bdim; j++) {
        int lj = sl[j];
        rank += (lj > myl) || (lj == myl && j < me);
    }
    g_order[rank] = me;
    if (me == 0) { g_counter = NWORK; g_done = 0; }
}

__global__ __launch_bounds__(Tdim, 2) void crf_batch_kernel(
    const float* __restrict__ feats,        // [B, L, T]
    const float* __restrict__ trans,        // [T, T]  trans[next, prev]
    const int*   __restrict__ tags,         // [B, L]
    const int*   __restrict__ lens,         // [B]
    float*       __restrict__ out)
{
    const int tid  = threadIdx.x;
    const int lane = tid & 31;
    const int w    = tid >> 5;

    __shared__ __align__(16) float gbuf[2][Tdim];      // warp-private slices
    __shared__ __align__(16) float part[2][4 * Tdim];  // partials [buf][k*128 + t]
    __shared__ float smax[4];
    __shared__ float ssum[4];
    __shared__ int   sh_job;
    __shared__ int   sh_last;

    // ---- et: exp(trans) for rows 4*lane..4*lane+3, cols [32w, 32w+32) ----
    unsigned long long et[64];
    #pragma unroll
    for (int tp = 0; tp < 4; tp++) {
        const float4* rowp = reinterpret_cast<const float4*>(
            trans + (4 * lane + tp) * Tdim + 32 * w);
        #pragma unroll
        for (int q = 0; q < 8; q++) {
            float4 v = rowp[q];
            et[tp * 16 + 2 * q]     = pack2(exp2f(v.x * LOG2E), exp2f(v.y * LOG2E));
            et[tp * 16 + 2 * q + 1] = pack2(exp2f(v.z * LOG2E), exp2f(v.w * LOG2E));
        }
    }
    // exp(trans[tid, START]) for the peeled first step
    const float etS = exp2f(trans[tid * Tdim + START_TAG] * LOG2E);

    int job = blockIdx.x;
    while (job < Bdim) {
        const int b     = g_order[job];
        const int len   = lens[b];
        const int lenm1 = len - 1;
        const float* emit = feats + (size_t)b * Ldim * Tdim + tid;

        // emission prefetch ring: ee[k] = exp(emit at step k)
        float ee[PF];
        #pragma unroll
        for (int k = 0; k < PF; k++)
            ee[k] = exp2f(emit[min(k, lenm1) * Tdim] * LOG2E);

        // ---- peel step 0: u_1[t] = ee_0[t] * exp(trans[t, START]), C_1 = 1 ----
        float g    = ee[0] * etS;
        float Macc = 0.0f;                   // accumulated log2 scale
        gbuf[1][tid] = g;                    // step i reads gbuf[i&1]
        ee[0] = exp2f(emit[min(PF, lenm1) * Tdim] * LOG2E);
        __syncthreads();

        // ---- iterations i = 1 .. PF-1 (ring warm-up) ----
        #pragma unroll
        for (int j = 1; j < PF; j++) {
            const int i = j;
            const int p = i & 1;
            const bool act = (i < len);                  // block-uniform

            float4 s4 = matvec_warp(&gbuf[p][32 * w], et);
            *reinterpret_cast<float4*>(&part[p][w * Tdim + 4 * lane]) = s4;
            float ecur = ee[j];
            ee[j] = exp2f(emit[min(i + PF, lenm1) * Tdim] * LOG2E);
            __syncthreads();                             // the ONLY barrier
            float s  = (part[p][0 * Tdim + tid] + part[p][1 * Tdim + tid])
                     + (part[p][2 * Tdim + tid] + part[p][3 * Tdim + tid]);
            float s0 = (part[p][0] + part[p][Tdim])
                     + (part[p][2 * Tdim] + part[p][3 * Tdim]);
            float u = s * (ecur * rcp_fast(s0));
            if (act) {
                g = u;
                Macc += __log2f(s0);
                gbuf[p ^ 1][tid] = u;                    // warp-private slice
            }
            __syncwarp();
        }

        // ---- main loop, blocks of PF ----
        for (int i0 = PF; i0 < len; i0 += PF) {
            #pragma unroll
            for (int j = 0; j < PF; j++) {
                const int i = i0 + j;
                const int p = i & 1;
                const bool act = (i < len);              // block-uniform

                float4 s4 = matvec_warp(&gbuf[p][32 * w], et);
                *reinterpret_cast<float4*>(&part[p][w * Tdim + 4 * lane]) = s4;
                float ecur = ee[j];
                ee[j] = exp2f(emit[min(i + PF, lenm1) * Tdim] * LOG2E);
                __syncthreads();
                float s  = (part[p][0 * Tdim + tid] + part[p][1 * Tdim + tid])
                         + (part[p][2 * Tdim + tid] + part[p][3 * Tdim + tid]);
                float s0 = (part[p][0] + part[p][Tdim])
                         + (part[p][2 * Tdim] + part[p][3 * Tdim]);
                float u = s * (ecur * rcp_fast(s0));
                if (act) {
                    g = u;
                    Macc += __log2f(s0);
                    gbuf[p ^ 1][tid] = u;
                }
                __syncwarp();
            }
        }
        __syncthreads();

        // fv[t] = ln2 * (log2(u_len) + Macc); u==0 (START row) -> -inf, OK in LSE
        float fv = (__log2f(g) + Macc) * LN2;

        float res = finish_batch(fv, len, b, tid, lane, w,
                                 feats, trans, tags, smax, ssum);
        if (tid == 0) {
            g_partial[b] = res;
            sh_job = atomicAdd(&g_counter, 1);
        }
        __syncthreads();
        job = sh_job;
        __syncthreads();
    }

    // ---- fused final reduction: last CTA to finish computes the mean ----
    __threadfence();
    if (tid == 0) sh_last = atomicAdd(&g_done, 1);
    __syncthreads();
    if (sh_last == NWORK - 1) {
        __threadfence();
        float v = 0.f;
        #pragma unroll
        for (int k = 0; k < Bdim / Tdim; k++)
            v += g_partial[k * Tdim + tid];
        #pragma unroll
        for (int o = 16; o > 0; o >>= 1)
            v += __shfl_xor_sync(0xffffffffu, v, o);
        if (lane == 0) ssum[w] = v;
        __syncthreads();
        if (tid == 0)
            out[0] = ((ssum[0] + ssum[1]) + (ssum[2] + ssum[3])) * (1.0f / (float)Bdim);
    }
}

extern "C" void kernel_launch(void* const* d_in, const int* in_sizes, int n_in,
                              void* d_out, int out_size)
{
    const float* feats = (const float*)d_in[0];
    const float* trans = (const float*)d_in[1];
    const int*   tags  = (const int*)d_in[2];
    const int*   lens  = (const int*)d_in[3];
    float* out = (float*)d_out;

    crf_schedule_kernel<<<8, 64>>>(lens);
    crf_batch_kernel<<<NWORK, Tdim>>>(feats, trans, tags, lens, out);
}

// round 13
// speedup vs baseline: 1.0623x; 1.0623x over previous
#include <cuda_runtime.h>
#include <string.h>

#define Bdim 512
#define Ldim 512
#define Tdim 128
#define START_TAG 126
#define STOP_TAG 127
#define LOG2E 1.4426950408889634f
#define LN2   0.6931471805599453f
#define PF 8              // emission prefetch depth / unroll factor
#define NWORK 304         // persistent CTAs (2 per SM)

__device__ float g_partial[Bdim];     // per-batch forward - gold
__device__ int   g_counter;           // work queue head
__device__ int   g_done;              // completion counter
__device__ int   g_order[Bdim];       // batch ids sorted by len desc

__device__ __forceinline__ void fma2(unsigned long long& d,
                                     unsigned long long a,
                                     unsigned long long b) {
    asm("fma.rn.f32x2 %0, %1, %2, %0;" : "+l"(d) : "l"(a), "l"(b));
}
__device__ __forceinline__ float rcp_fast(float x) {
    float r;
    asm("rcp.approx.f32 %0, %1;" : "=f"(r) : "f"(x));
    return r;
}
__device__ __forceinline__ unsigned long long pack2(float a, float b) {
    unsigned long long r;
    asm("mov.b64 %0, {%1,%2};" : "=l"(r) : "f"(a), "f"(b));
    return r;
}
__device__ __forceinline__ float hadd2(unsigned long long a) {
    float2 f; memcpy(&f, &a, 8);
    return f.x + f.y;
}

// Warp-split-K matvec via broadcast LDS from gslice = gbuf + 32*w.
// et[64]: rows 4*lane..4*lane+3 (16 f32x2 pairs each) over this warp's 32 cols.
__device__ __forceinline__ float4 matvec_warp(const float* gslice,
                                              const unsigned long long* et) {
    const ulonglong2* gb = reinterpret_cast<const ulonglong2*>(gslice);
    unsigned long long a0 = 0, a1 = 0, a2 = 0, a3 = 0;
    #pragma unroll
    for (int q = 0; q < 8; q++) {
        ulonglong2 uv = gb[q];            // broadcast LDS.128
        fma2(a0, et[2 * q],          uv.x);
        fma2(a0, et[2 * q + 1],      uv.y);
        fma2(a1, et[16 + 2 * q],     uv.x);
        fma2(a1, et[16 + 2 * q + 1], uv.y);
        fma2(a2, et[32 + 2 * q],     uv.x);
        fma2(a2, et[32 + 2 * q + 1], uv.y);
        fma2(a3, et[48 + 2 * q],     uv.x);
        fma2(a3, et[48 + 2 * q + 1], uv.y);
    }
    return make_float4(hadd2(a0), hadd2(a1), hadd2(a2), hadd2(a3));
}

// terminal LSE + gold score; returns forward_score - gold_score (all threads)
__device__ __forceinline__ float finish_batch(
    float fv, int len, int b, int t, int lane, int warp,
    const float* __restrict__ feats, const float* __restrict__ trans,
    const int* __restrict__ tags, float* smax, float* ssum)
{
    float term = fv + trans[START_TAG * Tdim + t];
    float m2 = term;
    #pragma unroll
    for (int o = 16; o > 0; o >>= 1)
        m2 = fmaxf(m2, __shfl_xor_sync(0xffffffffu, m2, o));
    if (lane == 0) smax[warp] = m2;
    __syncthreads();
    m2 = fmaxf(fmaxf(smax[0], smax[1]), fmaxf(smax[2], smax[3]));

    float ex = exp2f((term - m2) * LOG2E);
    #pragma unroll
    for (int o = 16; o > 0; o >>= 1)
        ex += __shfl_xor_sync(0xffffffffu, ex, o);
    if (lane == 0) ssum[warp] = ex;
    __syncthreads();
    float fwd = m2 + __logf((ssum[0] + ssum[1]) + (ssum[2] + ssum[3]));
    __syncthreads();

    float acc = 0.f;
    const int* tg = tags + b * Ldim;
    for (int j = t; j <= len; j += Tdim) {
        int pa, pb;
        if (j == 0)        { pa = START_TAG;   pb = tg[0];    }
        else if (j == len) { pa = tg[len - 1]; pb = STOP_TAG; }
        else               { pa = tg[j - 1];   pb = tg[j];    }
        acc += trans[pb * Tdim + pa];
    }
    for (int i = t; i < len; i += Tdim) {
        int tag = tg[i];
        acc += feats[((size_t)b * Ldim + i) * Tdim + tag];
    }
    #pragma unroll
    for (int o = 16; o > 0; o >>= 1)
        acc += __shfl_xor_sync(0xffffffffu, acc, o);
    if (lane == 0) ssum[warp] = acc;
    __syncthreads();
    float gold = (ssum[0] + ssum[1]) + (ssum[2] + ssum[3]);
    __syncthreads();
    return fwd - gold;
}

// rank batches by length (desc, stable) + reset counters. grid 8 x 64
__global__ __launch_bounds__(64) void crf_schedule_kernel(const int* __restrict__ lens)
{
    __shared__ int sl[Bdim];
    const int tb = threadIdx.x;
    for (int k = tb; k < Bdim; k += 64) sl[k] = lens[k];
    __syncthreads();
    const int me = blockIdx.x * 64 + tb;
    const int myl = sl[me];
    int rank = 0;
    #pragma unroll 8
    for (int j = 0; j < Bdim; j++) {
        int lj = sl[j];
        rank += (lj > myl) || (lj == myl && j < me);
    }
    g_order[rank] = me;
    if (me == 0) { g_counter = NWORK; g_done = 0; }
}

__global__ __launch_bounds__(Tdim, 2) void crf_batch_kernel(
    const float* __restrict__ feats,        // [B, L, T]
    const float* __restrict__ trans,        // [T, T]  trans[next, prev]
    const int*   __restrict__ tags,         // [B, L]
    const int*   __restrict__ lens,         // [B]
    float*       __restrict__ out)
{
    const int tid  = threadIdx.x;
    const int lane = tid & 31;
    const int w    = tid >> 5;

    __shared__ __align__(16) float gbuf[2][Tdim];      // warp-private slices
    __shared__ __align__(16) float part[2][4 * Tdim];  // partials [buf][k*128 + t]
    __shared__ float smax[4];
    __shared__ float ssum[4];
    __shared__ int   sh_job;
    __shared__ int   sh_last;

    // ---- et: exp(trans) for rows 4*lane..4*lane+3, cols [32w, 32w+32) ----
    unsigned long long et[64];
    #pragma unroll
    for (int tp = 0; tp < 4; tp++) {
        const float4* rowp = reinterpret_cast<const float4*>(
            trans + (4 * lane + tp) * Tdim + 32 * w);
        #pragma unroll
        for (int q = 0; q < 8; q++) {
            float4 v = rowp[q];
            et[tp * 16 + 2 * q]     = pack2(exp2f(v.x * LOG2E), exp2f(v.y * LOG2E));
            et[tp * 16 + 2 * q + 1] = pack2(exp2f(v.z * LOG2E), exp2f(v.w * LOG2E));
        }
    }
    // exp(trans[tid, START]) for the peeled first step
    const float etS = exp2f(trans[tid * Tdim + START_TAG] * LOG2E);

    int job = blockIdx.x;
    while (job < Bdim) {
        const int b     = g_order[job];
        const int len   = lens[b];
        const int lenm1 = len - 1;
        const float* emit = feats + (size_t)b * Ldim * Tdim + tid;

        // emission prefetch ring: ee[k] = exp(emit at step k)
        float ee[PF];
        #pragma unroll
        for (int k = 0; k < PF; k++)
            ee[k] = exp2f(emit[min(k, lenm1) * Tdim] * LOG2E);

        // ---- peel step 0: u_1[t] = ee_0[t] * exp(trans[t, START]), scale 1 ----
        float g    = ee[0] * etS;
        float Macc = 0.0f;                   // accumulated log2 scale
        float s0p  = 1.0f;                   // deferred normalizer (prev step's s[0])
        gbuf[1][tid] = g;                    // step i reads gbuf[i&1]
        ee[0] = exp2f(emit[min(PF, lenm1) * Tdim] * LOG2E);
        __syncthreads();

        // ---- iterations i = 1 .. PF-1 (ring warm-up) ----
        #pragma unroll
        for (int j = 1; j < PF; j++) {
            const int i = j;
            const int p = i & 1;
            const bool act = (i < len);                  // block-uniform

            float r = rcp_fast(s0p);                     // off-chain (hidden by matvec)
            float4 s4 = matvec_warp(&gbuf[p][32 * w], et);
            *reinterpret_cast<float4*>(&part[p][w * Tdim + 4 * lane]) = s4;
            float ecur = ee[j];
            ee[j] = exp2f(emit[min(i + PF, lenm1) * Tdim] * LOG2E);
            float f = ecur * r;
            __syncthreads();                             // the ONLY block barrier
            float s  = (part[p][0 * Tdim + tid] + part[p][1 * Tdim + tid])
                     + (part[p][2 * Tdim + tid] + part[p][3 * Tdim + tid]);
            float u = s * f;
            // next step's normalizer: this step's raw s at state 0 (off-chain)
            float s0 = (part[p][0] + part[p][Tdim])
                     + (part[p][2 * Tdim] + part[p][3 * Tdim]);
            if (act) {
                g = u;
                Macc += __log2f(s0p);
                gbuf[p ^ 1][tid] = u;                    // warp-private slice
            }
            s0p = s0;
            __syncwarp();
        }

        // ---- main loop, blocks of PF ----
        for (int i0 = PF; i0 < len; i0 += PF) {
            #pragma unroll
            for (int j = 0; j < PF; j++) {
                const int i = i0 + j;
                const int p = i & 1;
                const bool act = (i < len);              // block-uniform

                float r = rcp_fast(s0p);
                float4 s4 = matvec_warp(&gbuf[p][32 * w], et);
                *reinterpret_cast<float4*>(&part[p][w * Tdim + 4 * lane]) = s4;
                float ecur = ee[j];
                ee[j] = exp2f(emit[min(i + PF, lenm1) * Tdim] * LOG2E);
                float f = ecur * r;
                __syncthreads();
                float s  = (part[p][0 * Tdim + tid] + part[p][1 * Tdim + tid])
                         + (part[p][2 * Tdim + tid] + part[p][3 * Tdim + tid]);
                float u = s * f;
                float s0 = (part[p][0] + part[p][Tdim])
                         + (part[p][2 * Tdim] + part[p][3 * Tdim]);
                if (act) {
                    g = u;
                    Macc += __log2f(s0p);
                    gbuf[p ^ 1][tid] = u;
                }
                s0p = s0;
                __syncwarp();
            }
        }
        __syncthreads();

        // fv[t] = ln2 * (log2(u_len) + Macc); u==0 (START row) -> -inf, OK in LSE
        float fv = (__log2f(g) + Macc) * LN2;

        float res = finish_batch(fv, len, b, tid, lane, w,
                                 feats, trans, tags, smax, ssum);
        if (tid == 0) {
            g_partial[b] = res;
            sh_job = atomicAdd(&g_counter, 1);
        }
        __syncthreads();
        job = sh_job;
        __syncthreads();
    }

    // ---- fused final reduction: last CTA to finish computes the mean ----
    __threadfence();
    if (tid == 0) sh_last = atomicAdd(&g_done, 1);
    __syncthreads();
    if (sh_last == NWORK - 1) {
        __threadfence();
        float v = 0.f;
        #pragma unroll
        for (int k = 0; k < Bdim / Tdim; k++)
            v += g_partial[k * Tdim + tid];
        #pragma unroll
        for (int o = 16; o > 0; o >>= 1)
            v += __shfl_xor_sync(0xffffffffu, v, o);
        if (lane == 0) ssum[w] = v;
        __syncthreads();
        if (tid == 0)
            out[0] = ((ssum[0] + ssum[1]) + (ssum[2] + ssum[3])) * (1.0f / (float)Bdim);
    }
}

extern "C" void kernel_launch(void* const* d_in, const int* in_sizes, int n_in,
                              void* d_out, int out_size)
{
    const float* feats = (const float*)d_in[0];
    const float* trans = (const float*)d_in[1];
    const int*   tags  = (const int*)d_in[2];
    const int*   lens  = (const int*)d_in[3];
    float* out = (float*)d_out;

    crf_schedule_kernel<<<8, 64>>>(lens);
    crf_batch_kernel<<<NWORK, Tdim>>>(feats, trans, tags, lens, out);
}